// round 10
// baseline (speedup 1.0000x reference)
#include <cuda_runtime.h>
#include <math.h>

#define BB 4
#define LL 4096
#define DD 1024
#define NC1 128          // pass1 chunks per batch
#define LC1 (LL / NC1)   // 32 steps
#define NC3 64           // pass3 chunks per batch
#define LC3 (LL / NC3)   // 64 steps
#define LANES (DD / 2)   // 512 float2 lanes
#define TPB 128

#define N1 (4 * NC1)     // 512 pass1 blocks per batch (4 lane-blocks x 128 chunks)
#define N2 8             // 8 pass2 blocks per batch (1024 threads)
#define N3 (4 * NC3)     // 256 pass3 blocks per batch

// pass1 per-chunk local sums: BB*NC1*DD complex = 4 MB
__device__ float2 g_sum[BB * NC1 * DD];
// pass3 incoming states: BB*NC3*DD complex = 2 MB
__device__ float2 g_state[BB * NC3 * DD];

__device__ __forceinline__ float2 cmul(float2 a, float2 b) {
    return make_float2(fmaf(a.x, b.x, -a.y * b.y), fmaf(a.x, b.y, a.y * b.x));
}

__device__ __forceinline__ float2 get_phazor(const float* __restrict__ pr,
                                             const float* __restrict__ pi, int d) {
    float r = pr[d], i = pi[d];
    float mag = sqrtf(fmaf(r, r, i * i));
    float s = expf(-mag) / mag;
    return make_float2(r * s, i * s);
}

// step: S = p*S + x  (complex)
__device__ __forceinline__ void cstep(float2& S, const float2 p, const float xv) {
    float nr = fmaf(p.x, S.x, fmaf(-p.y, S.y, xv));
    float ni = fmaf(p.x, S.y, p.y * S.x);
    S.x = nr; S.y = ni;
}

// ---- role bodies ----

__device__ void role_pass1(int b, int ridx,
                           const float* __restrict__ x,
                           const float* __restrict__ pr,
                           const float* __restrict__ pi) {
    int lx = ridx & 3;            // lane-block 0..3
    int c  = ridx >> 2;           // chunk 0..127
    int lane = lx * TPB + threadIdx.x;   // 0..511
    int d0 = lane * 2;

    float2 p0 = get_phazor(pr, pi, d0);
    float2 p1 = get_phazor(pr, pi, d0 + 1);

    const float2* xp = (const float2*)x + ((size_t)b * LL + (size_t)c * LC1) * LANES + lane;

    float2 xs[2][8];
#pragma unroll
    for (int j = 0; j < 8; j++) xs[0][j] = xp[(size_t)j * LANES];

    float2 S0 = make_float2(0.f, 0.f);
    float2 S1 = make_float2(0.f, 0.f);
#pragma unroll
    for (int i = 0; i < LC1; i += 8) {
        int cur = (i >> 3) & 1;
        if (i + 8 < LC1) {
#pragma unroll
            for (int j = 0; j < 8; j++)
                xs[cur ^ 1][j] = xp[(size_t)(i + 8 + j) * LANES];
        }
#pragma unroll
        for (int j = 0; j < 8; j++) {
            cstep(S0, p0, xs[cur][j].x);
            cstep(S1, p1, xs[cur][j].y);
        }
    }
    float4 st = make_float4(S0.x, S0.y, S1.x, S1.y);
    ((float4*)g_sum)[((size_t)b * NC1 + c) * LANES + lane] = st;
}

__device__ void role_pass2(int b, int ridx,
                           const float* __restrict__ pr,
                           const float* __restrict__ pi) {
    int d = ridx * TPB + threadIdx.x;   // 0..1023

    float2 p = get_phazor(pr, pi, d);
    float2 A = p;
#pragma unroll
    for (int k = 0; k < 5; k++) A = cmul(A, A);      // p^32 = p^LC1

    float2 S = make_float2(0.f, 0.f);
#pragma unroll 1
    for (int cb = 0; cb < NC1; cb += 16) {
        float2 loc[16];
#pragma unroll
        for (int j = 0; j < 16; j++)
            loc[j] = g_sum[((size_t)b * NC1 + cb + j) * DD + d];
#pragma unroll
        for (int j = 0; j < 16; j++) {
            int c = cb + j;
            if ((c & 1) == 0)
                g_state[((size_t)b * NC3 + (c >> 1)) * DD + d] = S;
            float nr = fmaf(A.x, S.x, fmaf(-A.y, S.y, loc[j].x));
            float ni = fmaf(A.x, S.y, fmaf(A.y, S.x, loc[j].y));
            S.x = nr; S.y = ni;
        }
    }
}

template <bool CPLX>
__device__ void role_pass3(int b, int ridx,
                           const float* __restrict__ x,
                           const float* __restrict__ hr,
                           const float* __restrict__ hi,
                           const float* __restrict__ pr,
                           const float* __restrict__ pi,
                           const float* __restrict__ ir_,
                           const float* __restrict__ ii_,
                           float* __restrict__ out) {
    int cx = ridx & 3;
    int c  = ridx >> 2;                 // 0..63
    int lane = cx * TPB + threadIdx.x;  // 0..511
    int d0 = lane * 2;

    float2 p0 = get_phazor(pr, pi, d0);
    float2 p1 = get_phazor(pr, pi, d0 + 1);

    // pc = p^(c*LC3 + 1) via A = p^LC3, A^c binary pow (c uniform per block)
    float2 A0 = p0, A1 = p1;
#pragma unroll
    for (int k = 0; k < 6; k++) { A0 = cmul(A0, A0); A1 = cmul(A1, A1); }
    float2 Ae0 = make_float2(1.f, 0.f), Ae1 = make_float2(1.f, 0.f);
    float2 b0 = A0, b1 = A1;
    int e = c;
    while (e) {
        if (e & 1) { Ae0 = cmul(Ae0, b0); Ae1 = cmul(Ae1, b1); }
        b0 = cmul(b0, b0); b1 = cmul(b1, b1);
        e >>= 1;
    }
    float2 pc0 = cmul(p0, Ae0);
    float2 pc1 = cmul(p1, Ae1);

    float2 h0 = make_float2(hr[(size_t)b * DD + d0], hi[(size_t)b * DD + d0]);
    float2 h1 = make_float2(hr[(size_t)b * DD + d0 + 1], hi[(size_t)b * DD + d0 + 1]);
    float2 hp0 = cmul(h0, pc0);   // hidden * p^(t+1) at t = c*LC3
    float2 hp1 = cmul(h1, pc1);
    float2 i0 = make_float2(ir_[d0], ii_[d0]);
    float2 i1 = make_float2(ir_[d0 + 1], ii_[d0 + 1]);

    float4 sld = ((const float4*)g_state)[((size_t)b * NC3 + c) * LANES + lane];
    float2 S0 = make_float2(sld.x, sld.y);
    float2 S1 = make_float2(sld.z, sld.w);

    size_t pair0 = ((size_t)b * LL + (size_t)c * LC3) * LANES + lane;
    const float2* xp = (const float2*)x + pair0;

    float2 xs[2][8];
#pragma unroll
    for (int j = 0; j < 8; j++) xs[0][j] = __ldcs(xp + (size_t)j * LANES);

#pragma unroll
    for (int i = 0; i < LC3; i += 8) {
        int cur = (i >> 3) & 1;
        if (i + 8 < LC3) {
#pragma unroll
            for (int j = 0; j < 8; j++)
                xs[cur ^ 1][j] = __ldcs(xp + (size_t)(i + 8 + j) * LANES);
        }
#pragma unroll
        for (int j = 0; j < 8; j++) {
            cstep(S0, p0, xs[cur][j].x);
            cstep(S1, p1, xs[cur][j].y);
            float2 o0, o1;
            o0.x = fmaf(i0.x, S0.x, fmaf(-i0.y, S0.y, hp0.x));
            o0.y = fmaf(i0.x, S0.y, fmaf(i0.y, S0.x, hp0.y));
            o1.x = fmaf(i1.x, S1.x, fmaf(-i1.y, S1.y, hp1.x));
            o1.y = fmaf(i1.x, S1.y, fmaf(i1.y, S1.x, hp1.y));
            size_t pidx = pair0 + (size_t)(i + j) * LANES;
            if (CPLX) {
                __stcs((float4*)out + pidx, make_float4(o0.x, o0.y, o1.x, o1.y));
            } else {
                __stcs(out + pidx * 2, o0.x);
                __stcs(out + pidx * 2 + 1, o1.x);
            }
            // hp *= p
            float t0r = fmaf(hp0.x, p0.x, -hp0.y * p0.y);
            float t0i = fmaf(hp0.x, p0.y, hp0.y * p0.x);
            hp0.x = t0r; hp0.y = t0i;
            float t1r = fmaf(hp1.x, p1.x, -hp1.y * p1.y);
            float t1i = fmaf(hp1.x, p1.y, hp1.y * p1.x);
            hp1.x = t1r; hp1.y = t1i;
        }
    }
}

// ---- fused pipelined launch: blocks [0,n3) pass3(b3), [n3,n3+n1) pass1(b1),
//      [n3+n1, n3+n1+n2) pass2(b2) ----
template <bool CPLX>
__global__ void __launch_bounds__(TPB) pipe_kernel(const float* __restrict__ x,
                                                   const float* __restrict__ hr,
                                                   const float* __restrict__ hi,
                                                   const float* __restrict__ pr,
                                                   const float* __restrict__ pi,
                                                   const float* __restrict__ ir_,
                                                   const float* __restrict__ ii_,
                                                   float* __restrict__ out,
                                                   int b1, int b2, int b3,
                                                   int n1, int n2, int n3) {
    int bid = blockIdx.x;
    if (bid < n3) {
        role_pass3<CPLX>(b3, bid, x, hr, hi, pr, pi, ir_, ii_, out);
    } else if (bid < n3 + n1) {
        role_pass1(b1, bid - n3, x, pr, pi);
    } else {
        role_pass2(b2, bid - n3 - n1, pr, pi);
    }
}

extern "C" void kernel_launch(void* const* d_in, const int* in_sizes, int n_in,
                              void* d_out, int out_size) {
    const long long X_SZ = (long long)BB * LL * DD;  // 16,777,216
    const long long H_SZ = (long long)BB * DD;       // 4096
    const long long P_SZ = DD;                       // 1024

    int ix = -1;
    long long scale = 1;
    for (int i = 0; i < n_in; i++)
        if ((long long)in_sizes[i] == X_SZ) { ix = i; scale = 1; break; }
    if (ix < 0)
        for (int i = 0; i < n_in; i++)
            if ((long long)in_sizes[i] == X_SZ * 4) { ix = i; scale = 4; break; }

    const float *x, *hr, *hi, *pr, *pi, *ir_, *ii_;
    bool mapped = false;

    if (ix >= 0 && ix == n_in - 1 && n_in == 7) {
        // Alphabetical ordering
        hi  = (const float*)d_in[0];
        hr  = (const float*)d_in[1];
        pi  = (const float*)d_in[2];
        ii_ = (const float*)d_in[3];
        ir_ = (const float*)d_in[4];
        pr  = (const float*)d_in[5];
        x   = (const float*)d_in[6];
        mapped = true;
    } else if (ix >= 0) {
        x = (const float*)d_in[ix];
        const float* h_list[2] = {0, 0};
        const float* p_list[4] = {0, 0, 0, 0};
        int nh = 0, np = 0;
        for (int i = 0; i < n_in; i++) {
            if (i == ix) continue;
            long long s = (long long)in_sizes[i];
            if (s == H_SZ * scale && nh < 2) h_list[nh++] = (const float*)d_in[i];
            else if (s == P_SZ * scale && np < 4) p_list[np++] = (const float*)d_in[i];
        }
        if (nh == 2 && np == 4) {
            hr  = h_list[0]; hi  = h_list[1];
            pr  = p_list[0]; pi  = p_list[1];
            ir_ = p_list[2]; ii_ = p_list[3];
            mapped = true;
        }
    }
    if (!mapped) {
        x   = (const float*)d_in[0];
        hr  = (const float*)d_in[1];
        hi  = (const float*)d_in[2];
        pr  = (const float*)d_in[3];
        pi  = (const float*)d_in[4];
        ir_ = (const float*)d_in[5];
        ii_ = (const float*)d_in[6];
    }

    long long osz = (long long)out_size;
    bool cplx;
    if (osz == 2 * X_SZ || osz == 8 * X_SZ)       cplx = true;
    else if (osz == X_SZ || osz == 4 * X_SZ)      cplx = false;
    else                                          cplx = true;

    float* out = (float*)d_out;

    // pipeline schedule: per launch (b1 = pass1 batch, b2 = pass2 batch, b3 = pass3 batch)
    const int sched[BB + 2][3] = {
        {0, -1, -1},
        {1,  0, -1},
        {2,  1,  0},
        {3,  2,  1},
        {-1, 3,  2},
        {-1, -1, 3},
    };

    for (int k = 0; k < BB + 2; k++) {
        int b1 = sched[k][0], b2 = sched[k][1], b3 = sched[k][2];
        int n1 = (b1 >= 0) ? N1 : 0;
        int n2 = (b2 >= 0) ? N2 : 0;
        int n3 = (b3 >= 0) ? N3 : 0;
        int nblocks = n1 + n2 + n3;
        if (nblocks == 0) continue;
        if (cplx)
            pipe_kernel<true ><<<nblocks, TPB>>>(x, hr, hi, pr, pi, ir_, ii_, out,
                                                 b1, b2, b3, n1, n2, n3);
        else
            pipe_kernel<false><<<nblocks, TPB>>>(x, hr, hi, pr, pi, ir_, ii_, out,
                                                 b1, b2, b3, n1, n2, n3);
    }
}

// round 11
// speedup vs baseline: 1.5063x; 1.5063x over previous
#include <cuda_runtime.h>
#include <math.h>

#define BB 4
#define LL 4096
#define DD 1024
#define NC 64            // chunks
#define LC (LL / NC)     // 64 steps per chunk
#define LANES (DD / 2)   // 512 float2 lanes
#define TPB 128
#define ST 8             // cp.async pipeline stages (pass1)

// scratch: per (b, chunk, d) complex state. 2 MB. pass2 rewrites in place.
__device__ float2 g_scratch[BB * NC * DD];

__device__ __forceinline__ float2 cmul(float2 a, float2 b) {
    return make_float2(fmaf(a.x, b.x, -a.y * b.y), fmaf(a.x, b.y, a.y * b.x));
}

__device__ __forceinline__ float2 get_phazor(const float* __restrict__ pr,
                                             const float* __restrict__ pi, int d) {
    float r = pr[d], i = pi[d];
    float mag = sqrtf(fmaf(r, r, i * i));
    float s = expf(-mag) / mag;
    return make_float2(r * s, i * s);
}

// step: S = p*S + x  (complex)
__device__ __forceinline__ void cstep(float2& S, const float2 p, const float xv) {
    float nr = fmaf(p.x, S.x, fmaf(-p.y, S.y, xv));
    float ni = fmaf(p.x, S.y, p.y * S.x);
    S.x = nr; S.y = ni;
}

#define CP_ASYNC16(dst_u32, src_ptr) \
    asm volatile("cp.async.cg.shared.global [%0], [%1], 16;" \
                 :: "r"(dst_u32), "l"(src_ptr) : "memory")
#define CP_COMMIT() asm volatile("cp.async.commit_group;" ::: "memory")
#define CP_WAIT7()  asm volatile("cp.async.wait_group 7;" ::: "memory")

// -------- pass 1: per-chunk local recurrence, cp.async smem pipeline.
// Thread owns 4 consecutive d; per stage copies 16B; consumes only its own
// bytes so no block barrier is needed — wait_group is per-thread. --------
__global__ void __launch_bounds__(TPB) pass1_kernel(const float* __restrict__ x,
                                                    const float* __restrict__ pr,
                                                    const float* __restrict__ pi) {
    __shared__ float4 buf[ST][TPB];
    int tid = threadIdx.x;
    int lx = blockIdx.x;     // half-row 0..1
    int c  = blockIdx.y;
    int b  = blockIdx.z;
    int d0 = lx * 512 + tid * 4;

    float2 P0 = get_phazor(pr, pi, d0);
    float2 P1 = get_phazor(pr, pi, d0 + 1);
    float2 P2 = get_phazor(pr, pi, d0 + 2);
    float2 P3 = get_phazor(pr, pi, d0 + 3);

    // x as float4 rows: 256 float4 per (b,t) row; this thread's column:
    const float4* xp = (const float4*)x
        + ((size_t)b * LL + (size_t)c * LC) * (DD / 4) + lx * (TPB) + tid;

    unsigned sb = (unsigned)__cvta_generic_to_shared(&buf[0][tid]);
    const unsigned sstride = TPB * 16;   // bytes per stage

#pragma unroll
    for (int s = 0; s < ST; s++) {
        CP_ASYNC16(sb + s * sstride, xp + (size_t)s * (DD / 4));
        CP_COMMIT();
    }

    float2 S0 = make_float2(0.f, 0.f), S1 = S0, S2 = S0, S3 = S0;

#pragma unroll 1
    for (int t8 = 0; t8 < LC; t8 += ST) {
#pragma unroll
        for (int u = 0; u < ST; u++) {
            CP_WAIT7();
            float4 a = buf[u][tid];
            cstep(S0, P0, a.x);
            cstep(S1, P1, a.y);
            cstep(S2, P2, a.z);
            cstep(S3, P3, a.w);
            int tn = t8 + u + ST;
            if (tn < LC)
                CP_ASYNC16(sb + u * sstride, xp + (size_t)tn * (DD / 4));
            CP_COMMIT();
        }
    }

    // 4 complex sums = 32B contiguous (d0 multiple of 4)
    float4* gs = (float4*)(g_scratch + ((size_t)b * NC + c) * DD + d0);
    gs[0] = make_float4(S0.x, S0.y, S1.x, S1.y);
    gs[1] = make_float4(S2.x, S2.y, S3.x, S3.y);
}

// -------- pass 2: sequential combine across chunks (R7 verbatim) --------
__global__ void __launch_bounds__(256) pass2_kernel(const float* __restrict__ pr,
                                                    const float* __restrict__ pi) {
    int idx = blockIdx.x * blockDim.x + threadIdx.x; // 0..4095
    int d = idx & (DD - 1);
    int b = idx / DD;

    float2 p = get_phazor(pr, pi, d);
    float2 A = p;
#pragma unroll
    for (int k = 0; k < 6; k++) A = cmul(A, A);      // p^64 = p^LC

    float2 S = make_float2(0.f, 0.f);
#pragma unroll 1
    for (int cb = 0; cb < NC; cb += 16) {
        float2 loc[16];
#pragma unroll
        for (int j = 0; j < 16; j++)
            loc[j] = g_scratch[((size_t)b * NC + cb + j) * DD + d];
#pragma unroll
        for (int j = 0; j < 16; j++) {
            g_scratch[((size_t)b * NC + cb + j) * DD + d] = S;  // incoming state
            float nr = fmaf(A.x, S.x, fmaf(-A.y, S.y, loc[j].x));
            float ni = fmaf(A.x, S.y, fmaf(A.y, S.x, loc[j].y));
            S.x = nr; S.y = ni;
        }
    }
}

// -------- pass 3: recompute with true incoming state, write output --------
template <bool CPLX>
__global__ void __launch_bounds__(TPB) pass3_kernel(const float* __restrict__ x,
                                                    const float* __restrict__ hr,
                                                    const float* __restrict__ hi,
                                                    const float* __restrict__ pr,
                                                    const float* __restrict__ pi,
                                                    const float* __restrict__ ir_,
                                                    const float* __restrict__ ii_,
                                                    float* __restrict__ out) {
    int lane = blockIdx.x * TPB + threadIdx.x;  // 0..511
    int c = blockIdx.y;
    int b = blockIdx.z;
    int d0 = lane * 2;

    float2 p0 = get_phazor(pr, pi, d0);
    float2 p1 = get_phazor(pr, pi, d0 + 1);

    // pc = p^(c*LC + 1) via A = p^LC, A^c binary pow (c uniform per block)
    float2 A0 = p0, A1 = p1;
#pragma unroll
    for (int k = 0; k < 6; k++) { A0 = cmul(A0, A0); A1 = cmul(A1, A1); }
    float2 Ae0 = make_float2(1.f, 0.f), Ae1 = make_float2(1.f, 0.f);
    float2 b0 = A0, b1 = A1;
    int e = c;
    while (e) {
        if (e & 1) { Ae0 = cmul(Ae0, b0); Ae1 = cmul(Ae1, b1); }
        b0 = cmul(b0, b0); b1 = cmul(b1, b1);
        e >>= 1;
    }
    float2 pc0 = cmul(p0, Ae0);
    float2 pc1 = cmul(p1, Ae1);

    float2 h0 = make_float2(hr[(size_t)b * DD + d0], hi[(size_t)b * DD + d0]);
    float2 h1 = make_float2(hr[(size_t)b * DD + d0 + 1], hi[(size_t)b * DD + d0 + 1]);
    float2 hp0 = cmul(h0, pc0);   // hidden * p^(t+1) at t = c*LC
    float2 hp1 = cmul(h1, pc1);
    float2 i0 = make_float2(ir_[d0], ii_[d0]);
    float2 i1 = make_float2(ir_[d0 + 1], ii_[d0 + 1]);

    float4 sld = ((const float4*)g_scratch)[((size_t)b * NC + c) * LANES + lane];
    float2 S0 = make_float2(sld.x, sld.y);
    float2 S1 = make_float2(sld.z, sld.w);

    size_t pair0 = ((size_t)b * LL + (size_t)c * LC) * LANES + lane;
    const float2* xp = (const float2*)x + pair0;

    float2 xs[2][8];
#pragma unroll
    for (int j = 0; j < 8; j++) xs[0][j] = __ldcs(xp + (size_t)j * LANES);

#pragma unroll
    for (int i = 0; i < LC; i += 8) {
        int cur = (i >> 3) & 1;
        if (i + 8 < LC) {
#pragma unroll
            for (int j = 0; j < 8; j++)
                xs[cur ^ 1][j] = __ldcs(xp + (size_t)(i + 8 + j) * LANES);
        }
#pragma unroll
        for (int j = 0; j < 8; j++) {
            cstep(S0, p0, xs[cur][j].x);
            cstep(S1, p1, xs[cur][j].y);
            size_t pidx = pair0 + (size_t)(i + j) * LANES;
            if (CPLX) {
                float2 o0, o1;
                o0.x = fmaf(i0.x, S0.x, fmaf(-i0.y, S0.y, hp0.x));
                o0.y = fmaf(i0.x, S0.y, fmaf(i0.y, S0.x, hp0.y));
                o1.x = fmaf(i1.x, S1.x, fmaf(-i1.y, S1.y, hp1.x));
                o1.y = fmaf(i1.x, S1.y, fmaf(i1.y, S1.x, hp1.y));
                __stcs((float4*)out + pidx, make_float4(o0.x, o0.y, o1.x, o1.y));
            } else {
                // real-only output: one vectorized 8B store for (d0, d0+1)
                float r0 = fmaf(i0.x, S0.x, fmaf(-i0.y, S0.y, hp0.x));
                float r1 = fmaf(i1.x, S1.x, fmaf(-i1.y, S1.y, hp1.x));
                __stcs((float2*)out + pidx, make_float2(r0, r1));
            }
            // hp *= p
            float t0r = fmaf(hp0.x, p0.x, -hp0.y * p0.y);
            float t0i = fmaf(hp0.x, p0.y, hp0.y * p0.x);
            hp0.x = t0r; hp0.y = t0i;
            float t1r = fmaf(hp1.x, p1.x, -hp1.y * p1.y);
            float t1i = fmaf(hp1.x, p1.y, hp1.y * p1.x);
            hp1.x = t1r; hp1.y = t1i;
        }
    }
}

extern "C" void kernel_launch(void* const* d_in, const int* in_sizes, int n_in,
                              void* d_out, int out_size) {
    const long long X_SZ = (long long)BB * LL * DD;  // 16,777,216
    const long long H_SZ = (long long)BB * DD;       // 4096
    const long long P_SZ = DD;                       // 1024

    int ix = -1;
    long long scale = 1;
    for (int i = 0; i < n_in; i++)
        if ((long long)in_sizes[i] == X_SZ) { ix = i; scale = 1; break; }
    if (ix < 0)
        for (int i = 0; i < n_in; i++)
            if ((long long)in_sizes[i] == X_SZ * 4) { ix = i; scale = 4; break; }

    const float *x, *hr, *hi, *pr, *pi, *ir_, *ii_;
    bool mapped = false;

    if (ix >= 0 && ix == n_in - 1 && n_in == 7) {
        // Alphabetical ordering
        hi  = (const float*)d_in[0];
        hr  = (const float*)d_in[1];
        pi  = (const float*)d_in[2];
        ii_ = (const float*)d_in[3];
        ir_ = (const float*)d_in[4];
        pr  = (const float*)d_in[5];
        x   = (const float*)d_in[6];
        mapped = true;
    } else if (ix >= 0) {
        x = (const float*)d_in[ix];
        const float* h_list[2] = {0, 0};
        const float* p_list[4] = {0, 0, 0, 0};
        int nh = 0, np = 0;
        for (int i = 0; i < n_in; i++) {
            if (i == ix) continue;
            long long s = (long long)in_sizes[i];
            if (s == H_SZ * scale && nh < 2) h_list[nh++] = (const float*)d_in[i];
            else if (s == P_SZ * scale && np < 4) p_list[np++] = (const float*)d_in[i];
        }
        if (nh == 2 && np == 4) {
            hr  = h_list[0]; hi  = h_list[1];
            pr  = p_list[0]; pi  = p_list[1];
            ir_ = p_list[2]; ii_ = p_list[3];
            mapped = true;
        }
    }
    if (!mapped) {
        x   = (const float*)d_in[0];
        hr  = (const float*)d_in[1];
        hi  = (const float*)d_in[2];
        pr  = (const float*)d_in[3];
        pi  = (const float*)d_in[4];
        ir_ = (const float*)d_in[5];
        ii_ = (const float*)d_in[6];
    }

    long long osz = (long long)out_size;
    bool cplx;
    if (osz == 2 * X_SZ || osz == 8 * X_SZ)       cplx = true;
    else if (osz == X_SZ || osz == 4 * X_SZ)      cplx = false;
    else                                          cplx = true;

    float* out = (float*)d_out;

    dim3 grid1(2, NC, BB);             // (2, 64, 4) = 512 blocks x 128 threads
    pass1_kernel<<<grid1, TPB>>>(x, pr, pi);
    pass2_kernel<<<(BB * DD) / 256, 256>>>(pr, pi);
    dim3 grid3(LANES / TPB, NC, BB);   // (4, 64, 4) = 1024 blocks x 128 threads
    if (cplx)
        pass3_kernel<true ><<<grid3, TPB>>>(x, hr, hi, pr, pi, ir_, ii_, out);
    else
        pass3_kernel<false><<<grid3, TPB>>>(x, hr, hi, pr, pi, ir_, ii_, out);
}